// round 5
// baseline (speedup 1.0000x reference)
#include <cuda_runtime.h>
#include <math.h>

typedef unsigned long long ull;
typedef unsigned int uint;
#define DV __device__ __forceinline__

// ---------------- scratch (device globals; no allocations) ----------------
__device__ float g_a1[8 * 128 * 256];
__device__ float g_b1[8 * 128 * 256];
__device__ float g_a2[8 * 256 * 256];
__device__ float g_b2[8 * 256 * 256];
__device__ float g_np[8 * 256 * 8];

DV float lrelu(float x) { return x > 0.f ? x : 0.33f * x; }
DV ull ffma2(ull a, ull b, ull c) {
    ull d; asm("fma.rn.f32x2 %0,%1,%2,%3;" : "=l"(d) : "l"(a), "l"(b), "l"(c)); return d;
}
DV ull pack2(float x, float y) {
    ull d; asm("mov.b64 %0,{%1,%2};" : "=l"(d) : "r"(__float_as_uint(x)), "r"(__float_as_uint(y))); return d;
}
DV float2 unpk(ull v) {
    float2 f; asm("mov.b64 {%0,%1},%2;" : "=f"(f.x), "=f"(f.y) : "l"(v)); return f;
}

// ---------------- k1: layer-1 rank terms ----------------
// a1[b,c,i] = sum_j x[b,i,j]*w1a[c,j] + b1a[c] ; b1[b,c,j] = sum_i x[b,i,j]*w1b[c,i] + b1b[c]
__global__ void __launch_bounds__(256) k1(const float* __restrict__ x,
                                          const float* __restrict__ w1a, const float* __restrict__ b1a,
                                          const float* __restrict__ w1b, const float* __restrict__ b1b) {
    __shared__ float wa[256], wb[256];
    int b = blockIdx.x, c = blockIdx.y, t = threadIdx.x;
    wa[t] = w1a[c * 256 + t];
    wb[t] = w1b[c * 256 + t];
    __syncthreads();
    const float* xb = x + b * 65536;
    float aA = 0.f, aB = 0.f;
    const float4* xr = (const float4*)(xb + t * 256);
#pragma unroll 8
    for (int j4 = 0; j4 < 64; j4++) {
        float4 v = xr[j4];
        aA += v.x * wa[j4 * 4] + v.y * wa[j4 * 4 + 1] + v.z * wa[j4 * 4 + 2] + v.w * wa[j4 * 4 + 3];
    }
#pragma unroll 8
    for (int i = 0; i < 256; i++) aB += xb[i * 256 + t] * wb[i];
    g_a1[(b * 128 + c) * 256 + t] = aA + b1a[c];
    g_b1[(b * 128 + c) * 256 + t] = aB + b1b[c];
}

// ---------------- k2: layer-2 generated-operand GEMM (the hot kernel) ----------------
// mode0: a2[b,p,t] = sum_{c,s} lrelu(a1[c,t]+b1[c,s])*w2a[p,c,s] + b2a[p]
// mode1: b2[b,p,t] = sum_{c,s} lrelu(b1[c,t]+a1[c,s])*w2b[p,c,s] + b2b[p]
__global__ void __launch_bounds__(256) k2(const float* __restrict__ w2a, const float* __restrict__ b2a,
                                          const float* __restrict__ w2b, const float* __restrict__ b2b) {
    extern __shared__ ull sm[];
    ull* Wt2 = sm;            // [64 s][33] p-pair packed (pad -> conflict-free)
    ull* Ssd = sm + 64 * 33;  // [64 s][64 t] duplicated {v,v}

    int pb = blockIdx.x * 64, tb = blockIdx.y * 64;
    int b = blockIdx.z >> 1, mode = blockIdx.z & 1;
    const float* u = (mode ? g_b1 : g_a1) + b * 32768;
    const float* v = (mode ? g_a1 : g_b1) + b * 32768;
    const float* W = mode ? w2b : w2a;
    const float* bias = mode ? b2b : b2a;
    float* outp = (mode ? g_b2 : g_a2) + b * 65536;

    int tid = threadIdx.x;
    int tx = tid & 31, py = tid >> 5;   // inner-loop mapping
    int s4l = tid & 7, pl = tid >> 3;   // W loader mapping (pl 0..31)
    int tl = tid & 63, sg = tid >> 6;   // S generator mapping

    ull acc[4][2];
#pragma unroll
    for (int j = 0; j < 4; j++) { acc[j][0] = 0ULL; acc[j][1] = 0ULL; }

    for (int c = 0; c < 128; c++) {
        const float* uc = u + c * 256 + tb;
        const float* vc = v + c * 256;
        const float* Wc = W + c * 256;
        for (int sb = 0; sb < 256; sb += 64) {
            __syncthreads();
            // ---- load W chunk transposed + pair-packed: Wt2[s][pp] = {W[2pp][s], W[2pp+1][s]}
#pragma unroll
            for (int q = 0; q < 2; q++) {
                int p = pl + 32 * q;
#pragma unroll
                for (int n2 = 0; n2 < 2; n2++) {
                    int s4 = s4l + 8 * n2;
                    float4 f = *(const float4*)(Wc + (pb + p) * 32768 + sb + s4 * 4);
                    ull h0 = __shfl_xor_sync(0xffffffffu, ((ull*)&f)[0], 8);
                    ull h1 = __shfl_xor_sync(0xffffffffu, ((ull*)&f)[1], 8);
                    float4 g; ((ull*)&g)[0] = h0; ((ull*)&g)[1] = h1;  // partner row (p^1)
                    int pp = (pl >> 1) + 16 * q;
                    if ((pl & 1) == 0) {
                        Wt2[(s4 * 4 + 0) * 33 + pp] = pack2(f.x, g.x);
                        Wt2[(s4 * 4 + 1) * 33 + pp] = pack2(f.y, g.y);
                    } else {
                        Wt2[(s4 * 4 + 2) * 33 + pp] = pack2(g.z, f.z);
                        Wt2[(s4 * 4 + 3) * 33 + pp] = pack2(g.w, f.w);
                    }
                }
            }
            // ---- generate S tile, duplicated for packed FMA
            float ut = uc[tl];
#pragma unroll
            for (int it = 0; it < 16; it++) {
                int s = sg * 16 + it;
                float sv = lrelu(ut + vc[sb + s]);
                Ssd[s * 64 + tl] = pack2(sv, sv);
            }
            __syncthreads();
            // ---- inner product: 8 packed FMAs per k
#pragma unroll 8
            for (int k = 0; k < 64; k++) {
                ull s0 = Ssd[k * 64 + tx];
                ull s1 = Ssd[k * 64 + tx + 32];
                const ull* wr = &Wt2[k * 33 + py * 4];
#pragma unroll
                for (int j = 0; j < 4; j++) {
                    ull w = wr[j];
                    acc[j][0] = ffma2(w, s0, acc[j][0]);
                    acc[j][1] = ffma2(w, s1, acc[j][1]);
                }
            }
        }
    }
#pragma unroll
    for (int j = 0; j < 4; j++) {
        int p0 = pb + 2 * (py * 4 + j);
        float2 f0 = unpk(acc[j][0]), f1 = unpk(acc[j][1]);
        outp[p0 * 256 + tb + tx] = f0.x + bias[p0];
        outp[(p0 + 1) * 256 + tb + tx] = f0.y + bias[p0 + 1];
        outp[p0 * 256 + tb + tx + 32] = f1.x + bias[p0];
        outp[(p0 + 1) * 256 + tb + tx + 32] = f1.y + bias[p0 + 1];
    }
}

// ---------------- kz: zero the e2n accumulator ----------------
__global__ void kz() {
    int i = blockIdx.x * blockDim.x + threadIdx.x;
    if (i < 8 * 256 * 8) g_np[i] = 0.f;
}

// ---------------- k3: e2n contraction ----------------
// np[b,i,q] += sum_{c,j} lrelu(a2[b,c,i]+b2[b,c,j]) * e2n_w[q,c,j]
__global__ void __launch_bounds__(256) k3(const float* __restrict__ ew) {
    __shared__ float Bsm[256];
    __shared__ ull Esm[256 * 4];
    int b = blockIdx.x, pc = blockIdx.y, tid = threadIdx.x;
    ull a4[4] = {0ULL, 0ULL, 0ULL, 0ULL};
    for (int p = pc * 8; p < pc * 8 + 8; p++) {
        __syncthreads();
        Bsm[tid] = g_b2[(b * 256 + p) * 256 + tid];
        float e[8];
#pragma unroll
        for (int q = 0; q < 8; q++) e[q] = ew[q * 65536 + p * 256 + tid];
#pragma unroll
        for (int q = 0; q < 4; q++) Esm[tid * 4 + q] = pack2(e[2 * q], e[2 * q + 1]);
        __syncthreads();
        float ai = g_a2[(b * 256 + p) * 256 + tid];
#pragma unroll 4
        for (int j = 0; j < 256; j++) {
            float t = lrelu(ai + Bsm[j]);
            ull ts = pack2(t, t);
            const ull* er = &Esm[j * 4];
            a4[0] = ffma2(er[0], ts, a4[0]);
            a4[1] = ffma2(er[1], ts, a4[1]);
            a4[2] = ffma2(er[2], ts, a4[2]);
            a4[3] = ffma2(er[3], ts, a4[3]);
        }
    }
    float* dst = &g_np[b * 2048 + tid * 8];
#pragma unroll
    for (int q = 0; q < 4; q++) {
        float2 f = unpk(a4[q]);
        atomicAdd(dst + 2 * q, f.x);
        atomicAdd(dst + 2 * q + 1, f.y);
    }
}

// ---------------- k4: GCN / pooling / readout / MLP tail (one block per batch) ----------------
__global__ void __launch_bounds__(256) k4(const float* __restrict__ x, const float* __restrict__ e2n_b,
    const float* __restrict__ a11_w, const float* __restrict__ a11_b,
    const float* __restrict__ a12_w, const float* __restrict__ a12_b,
    const float* __restrict__ g1_w,  const float* __restrict__ g1_b,
    const float* __restrict__ a21_w, const float* __restrict__ a21_b,
    const float* __restrict__ a22_w, const float* __restrict__ a22_b,
    const float* __restrict__ d1_w,  const float* __restrict__ d1_b,
    const float* __restrict__ d2_w,  const float* __restrict__ d2_b,
    const float* __restrict__ d3_w,  const float* __restrict__ d3_b,
    float* __restrict__ out) {
    __shared__ uint  m0[256][8];
    __shared__ float nod[256][8];
    __shared__ float dg0[256];
    __shared__ float tp[256];
    __shared__ float sc[256];
    __shared__ float t8[256][8];
    __shared__ int   sel[128];
    __shared__ float hg[128][8];
    __shared__ float on[128][8];
    __shared__ uint  m1[128][4];
    __shared__ float dg1[128];
    __shared__ float z[16];
    __shared__ float z1[128];
    __shared__ float z2[64];

    int b = blockIdx.x, t = threadIdx.x;
    const float* xb = x + b * 65536;

    // adjacency bitmask, degrees, node features
    {
        int d = 0;
#pragma unroll
        for (int w = 0; w < 8; w++) {
            uint u = 0;
            for (int l = 0; l < 32; l++)
                if (xb[t * 256 + w * 32 + l] > 0.f) u |= (1u << l);
            m0[t][w] = u; d += __popc(u);
        }
        dg0[t] = (float)d;
#pragma unroll
        for (int f = 0; f < 8; f++) nod[t][f] = lrelu(g_np[b * 2048 + t * 8 + f] + e2n_b[f]);
    }
    __syncthreads();
    // a11: gn @ (nodes @ a11_w.T)
    {
        float s = 0;
#pragma unroll
        for (int f = 0; f < 8; f++) s += nod[t][f] * a11_w[f];
        tp[t] = s / dg0[t];
    }
    __syncthreads();
    {
        float s = 0;
        for (int j = 0; j < 256; j++) if ((m0[t][j >> 5] >> (j & 31)) & 1) s += tp[j];
        sc[t] = lrelu(s + a11_b[0]);
    }
    __syncthreads();
    // a12 + sigmoid
    tp[t] = sc[t] * a12_w[0] / dg0[t];
    __syncthreads();
    {
        float s = 0;
        for (int j = 0; j < 256; j++) if ((m0[t][j >> 5] >> (j & 31)) & 1) s += tp[j];
        sc[t] = 1.f / (1.f + expf(-(s + a12_b[0])));
    }
    __syncthreads();
    // stable top-128 (value desc, index asc)
    {
        float my = sc[t]; int r = 0;
        for (int j = 0; j < 256; j++) {
            float vj = sc[j];
            r += (vj > my) || (vj == my && j < t);
        }
        if (r < 128) sel[r] = t;
    }
    __syncthreads();
    // pooled features: out = h*s + h
    for (int idx = t; idx < 1024; idx += 256) {
        int r = idx >> 3, f = idx & 7; int i = sel[r];
        on[r][f] = nod[i][f] * (1.f + sc[i]);
    }
    // pooled adjacency bitmask + degrees
    if (t < 128) {
        int i = sel[t], d = 0;
#pragma unroll
        for (int w = 0; w < 4; w++) {
            uint u = 0;
            for (int l = 0; l < 32; l++) {
                int j = sel[w * 32 + l];
                u |= ((m0[i][j >> 5] >> (j & 31)) & 1u) << l;
            }
            m1[t][w] = u; d += __popc(u);
        }
        dg1[t] = (float)d;
    }
    __syncthreads();
    // readout sum1
    if (t < 8) {
        float mx = -1e30f, sm = 0;
        for (int r = 0; r < 128; r++) { float v = on[r][t]; mx = fmaxf(mx, v); sm += v; }
        z[t] = mx; z[8 + t] = sm * (1.f / 128.f);
    }
    __syncthreads();
    // h2 = gcn(out, g1, g1_w, g1_b)
    for (int idx = t; idx < 1024; idx += 256) {
        int r2 = idx >> 3, fo = idx & 7;
        float s = 0;
#pragma unroll
        for (int f = 0; f < 8; f++) s += on[r2][f] * g1_w[fo * 8 + f];
        t8[r2][fo] = s / dg1[r2];
    }
    __syncthreads();
    for (int idx = t; idx < 1024; idx += 256) {
        int r = idx >> 3, fo = idx & 7;
        float s = 0;
        for (int j = 0; j < 128; j++) if ((m1[r][j >> 5] >> (j & 31)) & 1) s += t8[j][fo];
        hg[r][fo] = s + g1_b[fo];
    }
    __syncthreads();
    // a21 / a22 scores
    if (t < 128) {
        float s = 0;
#pragma unroll
        for (int f = 0; f < 8; f++) s += hg[t][f] * a21_w[f];
        tp[t] = s / dg1[t];
    }
    __syncthreads();
    if (t < 128) {
        float s = 0;
        for (int j = 0; j < 128; j++) if ((m1[t][j >> 5] >> (j & 31)) & 1) s += tp[j];
        sc[t] = lrelu(s + a21_b[0]);
    }
    __syncthreads();
    if (t < 128) tp[t] = sc[t] * a22_w[0] / dg1[t];
    __syncthreads();
    if (t < 128) {
        float s = 0;
        for (int j = 0; j < 128; j++) if ((m1[t][j >> 5] >> (j & 31)) & 1) s += tp[j];
        sc[t] = 1.f / (1.f + expf(-(s + a22_b[0])));
    }
    __syncthreads();
    // stable top-64
    if (t < 128) {
        float my = sc[t]; int r = 0;
        for (int j = 0; j < 128; j++) {
            float vj = sc[j];
            r += (vj > my) || (vj == my && j < t);
        }
        if (r < 64) sel[r] = t;
    }
    __syncthreads();
    for (int idx = t; idx < 512; idx += 256) {
        int r = idx >> 3, f = idx & 7; int i = sel[r];
        on[r][f] = hg[i][f] * (1.f + sc[i]);
    }
    __syncthreads();
    if (t < 8) {
        float mx = -1e30f, sm = 0;
        for (int r = 0; r < 64; r++) { float v = on[r][t]; mx = fmaxf(mx, v); sm += v; }
        z[t] += mx; z[8 + t] += sm * (1.f / 64.f);
    }
    __syncthreads();
    // MLP
    if (t < 128) {
        float s = d1_b[t];
#pragma unroll
        for (int f = 0; f < 16; f++) s += z[f] * d1_w[t * 16 + f];
        z1[t] = lrelu(s);
    }
    __syncthreads();
    if (t < 64) {
        float s = d2_b[t];
        for (int f = 0; f < 128; f++) s += z1[f] * d2_w[t * 128 + f];
        z2[t] = lrelu(s);
    }
    __syncthreads();
    if (t == 0) {
        float s = d3_b[0];
        for (int f = 0; f < 64; f++) s += z2[f] * d3_w[f];
        out[b] = s;
    }
}

// ---------------- launcher ----------------
extern "C" void kernel_launch(void* const* d_in, const int* in_sizes, int n_in,
                              void* d_out, int out_size) {
    const float* x    = (const float*)d_in[0];
    const float* w1a  = (const float*)d_in[1];
    const float* b1a  = (const float*)d_in[2];
    const float* w1b  = (const float*)d_in[3];
    const float* b1b  = (const float*)d_in[4];
    const float* w2a  = (const float*)d_in[5];
    const float* b2a  = (const float*)d_in[6];
    const float* w2b  = (const float*)d_in[7];
    const float* b2b  = (const float*)d_in[8];
    const float* e2nw = (const float*)d_in[9];
    const float* e2nb = (const float*)d_in[10];
    const float* a11w = (const float*)d_in[11];
    const float* a11b = (const float*)d_in[12];
    const float* a12w = (const float*)d_in[13];
    const float* a12b = (const float*)d_in[14];
    const float* g1w  = (const float*)d_in[15];
    const float* g1b  = (const float*)d_in[16];
    const float* a21w = (const float*)d_in[17];
    const float* a21b = (const float*)d_in[18];
    const float* a22w = (const float*)d_in[19];
    const float* a22b = (const float*)d_in[20];
    const float* d1w  = (const float*)d_in[21];
    const float* d1b  = (const float*)d_in[22];
    const float* d2w  = (const float*)d_in[23];
    const float* d2b  = (const float*)d_in[24];
    const float* d3w  = (const float*)d_in[25];
    const float* d3b  = (const float*)d_in[26];

    const int k2_smem = (64 * 33 + 64 * 64) * (int)sizeof(ull);  // 49664 B
    cudaFuncSetAttribute(k2, cudaFuncAttributeMaxDynamicSharedMemorySize, k2_smem);

    k1<<<dim3(8, 128), 256>>>(x, w1a, b1a, w1b, b1b);
    kz<<<16, 1024>>>();
    k2<<<dim3(4, 4, 16), 256, k2_smem>>>(w2a, b2a, w2b, b2b);
    k3<<<dim3(8, 32), 256>>>(e2nw);   // FIX: 32 channel-chunks (was 16 -> dropped half the channels)
    k4<<<8, 256>>>(x, e2nb, a11w, a11b, a12w, a12b, g1w, g1b, a21w, a21b,
                   a22w, a22b, d1w, d1b, d2w, d2b, d3w, d3b, (float*)d_out);
}

// round 6
// speedup vs baseline: 1.5196x; 1.5196x over previous
#include <cuda_runtime.h>
#include <math.h>

typedef unsigned long long ull;
typedef unsigned int uint;
#define DV __device__ __forceinline__

// ---------------- scratch (device globals; no allocations) ----------------
__device__ float g_a1[8 * 128 * 256];
__device__ float g_b1[8 * 128 * 256];
__device__ float g_a2[8 * 256 * 256];
__device__ float g_b2[8 * 256 * 256];
__device__ float g_np[8 * 256 * 8];
__device__ float g_part[8][16][65536];   // k-split partials for k2

DV float lrelu(float x) { return x > 0.f ? x : 0.33f * x; }
DV ull ffma2(ull a, ull b, ull c) {
    ull d; asm("fma.rn.f32x2 %0,%1,%2,%3;" : "=l"(d) : "l"(a), "l"(b), "l"(c)); return d;
}
DV ull pack2(float x, float y) {
    ull d; asm("mov.b64 %0,{%1,%2};" : "=l"(d) : "r"(__float_as_uint(x)), "r"(__float_as_uint(y))); return d;
}
DV float2 unpk(ull v) {
    float2 f; asm("mov.b64 {%0,%1},%2;" : "=f"(f.x), "=f"(f.y) : "l"(v)); return f;
}

// ---------------- k1: layer-1 rank terms ----------------
__global__ void __launch_bounds__(256) k1(const float* __restrict__ x,
                                          const float* __restrict__ w1a, const float* __restrict__ b1a,
                                          const float* __restrict__ w1b, const float* __restrict__ b1b) {
    __shared__ float wa[256], wb[256];
    int b = blockIdx.x, c = blockIdx.y, t = threadIdx.x;
    wa[t] = w1a[c * 256 + t];
    wb[t] = w1b[c * 256 + t];
    __syncthreads();
    const float* xb = x + b * 65536;
    float aA = 0.f, aB = 0.f;
    const float4* xr = (const float4*)(xb + t * 256);
#pragma unroll 8
    for (int j4 = 0; j4 < 64; j4++) {
        float4 v = xr[j4];
        aA += v.x * wa[j4 * 4] + v.y * wa[j4 * 4 + 1] + v.z * wa[j4 * 4 + 2] + v.w * wa[j4 * 4 + 3];
    }
#pragma unroll 8
    for (int i = 0; i < 256; i++) aB += xb[i * 256 + t] * wb[i];
    g_a1[(b * 128 + c) * 256 + t] = aA + b1a[c];
    g_b1[(b * 128 + c) * 256 + t] = aB + b1b[c];
}

// ---------------- k2: layer-2 generated-operand GEMM, 128x128 tile, k-split 8 ----------------
// mode0: a2[b,p,t] = sum_{c,s} lrelu(a1[c,t]+b1[c,s])*w2a[p,c,s]
// mode1: b2[b,p,t] = sum_{c,s} lrelu(b1[c,t]+a1[c,s])*w2b[p,c,s]
__global__ void __launch_bounds__(256, 2) k2(const float* __restrict__ w2a,
                                             const float* __restrict__ w2b) {
    extern __shared__ float sm[];
    float* Wsm = sm;          // [64 s][128 p]
    float* Ssm = sm + 8192;   // [64 s][128 t]

    int pb = (blockIdx.x & 1) * 128, tb = (blockIdx.x >> 1) * 128;
    int slice = blockIdx.y;           // 0..7 (16 c each)
    int cs = slice * 16;
    int bm = blockIdx.z;              // 0..15
    int b = bm >> 1, mode = bm & 1;
    const float* u = (mode ? g_b1 : g_a1) + b * 32768;
    const float* v = (mode ? g_a1 : g_b1) + b * 32768;
    const float* W = mode ? w2b : w2a;

    int tid = threadIdx.x;
    int lane = tid & 31, wid = tid >> 5;
    int wp = tid >> 1, wh = (tid & 1) * 32;        // W stage: p row + s-half
    int tcol = tid & 127, sh2 = (tid >> 7) * 32;   // S gen: t col + s-half

    ull acc[8][4];
#pragma unroll
    for (int j = 0; j < 8; j++)
#pragma unroll
        for (int t = 0; t < 4; t++) acc[j][t] = 0ULL;

    for (int c = cs; c < cs + 16; c++) {
        float ur = u[c * 256 + tb + tcol];
        const float* vc = v + c * 256;
        const float* wr = W + (pb + wp) * 32768 + c * 256 + wh;
        for (int sb = 0; sb < 256; sb += 64) {
            __syncthreads();
            // stage W chunk transposed: Wsm[s][p]  (gmem coalesced along s)
#pragma unroll
            for (int m = 0; m < 8; m++) {
                float4 f = *(const float4*)(wr + sb + m * 4);
                Wsm[(wh + m * 4 + 0) * 128 + wp] = f.x;
                Wsm[(wh + m * 4 + 1) * 128 + wp] = f.y;
                Wsm[(wh + m * 4 + 2) * 128 + wp] = f.z;
                Wsm[(wh + m * 4 + 3) * 128 + wp] = f.w;
            }
            // generate S chunk: Ssm[s][t] = lrelu(u[t] + v[s])
#pragma unroll
            for (int m = 0; m < 8; m++) {
                float4 vv = *(const float4*)(vc + sb + sh2 + m * 4);
                Ssm[(sh2 + m * 4 + 0) * 128 + tcol] = lrelu(ur + vv.x);
                Ssm[(sh2 + m * 4 + 1) * 128 + tcol] = lrelu(ur + vv.y);
                Ssm[(sh2 + m * 4 + 2) * 128 + tcol] = lrelu(ur + vv.z);
                Ssm[(sh2 + m * 4 + 3) * 128 + tcol] = lrelu(ur + vv.w);
            }
            __syncthreads();
            // inner product: 5 LDS + 32 FFMA2 per k
#pragma unroll 8
            for (int k = 0; k < 64; k++) {
                float4 s4 = *(const float4*)&Ssm[k * 128 + 4 * lane];
                ull sd0 = pack2(s4.x, s4.x), sd1 = pack2(s4.y, s4.y);
                ull sd2 = pack2(s4.z, s4.z), sd3 = pack2(s4.w, s4.w);
#pragma unroll
                for (int m = 0; m < 4; m++) {
                    float4 wf = *(const float4*)&Wsm[k * 128 + wid * 16 + m * 4];
                    ull w0, w1;
                    w0 = pack2(wf.x, wf.y);
                    w1 = pack2(wf.z, wf.w);
                    acc[2 * m][0] = ffma2(w0, sd0, acc[2 * m][0]);
                    acc[2 * m][1] = ffma2(w0, sd1, acc[2 * m][1]);
                    acc[2 * m][2] = ffma2(w0, sd2, acc[2 * m][2]);
                    acc[2 * m][3] = ffma2(w0, sd3, acc[2 * m][3]);
                    acc[2 * m + 1][0] = ffma2(w1, sd0, acc[2 * m + 1][0]);
                    acc[2 * m + 1][1] = ffma2(w1, sd1, acc[2 * m + 1][1]);
                    acc[2 * m + 1][2] = ffma2(w1, sd2, acc[2 * m + 1][2]);
                    acc[2 * m + 1][3] = ffma2(w1, sd3, acc[2 * m + 1][3]);
                }
            }
        }
    }
    // epilogue: write partials (coalesced float4 along t)
    float* dst = &g_part[slice][bm][0];
#pragma unroll
    for (int j = 0; j < 8; j++) {
        int p0 = pb + wid * 16 + 2 * j;
        float2 f0 = unpk(acc[j][0]), f1 = unpk(acc[j][1]);
        float2 f2 = unpk(acc[j][2]), f3 = unpk(acc[j][3]);
        float4 lo = make_float4(f0.x, f1.x, f2.x, f3.x);
        float4 hi = make_float4(f0.y, f1.y, f2.y, f3.y);
        *(float4*)&dst[p0 * 256 + tb + 4 * lane] = lo;
        *(float4*)&dst[(p0 + 1) * 256 + tb + 4 * lane] = hi;
    }
}

// ---------------- kr: deterministic k-split reduction + bias ----------------
__global__ void __launch_bounds__(256) kr(const float* __restrict__ b2a,
                                          const float* __restrict__ b2b) {
    int idx = (blockIdx.x * 256 + threadIdx.x) * 4;   // 1024 blocks -> 1,048,576 floats
    int bm = idx >> 16, rem = idx & 65535;
    int p = rem >> 8;
    float4 s = *(const float4*)&g_part[0][bm][rem];
#pragma unroll
    for (int sl = 1; sl < 8; sl++) {
        float4 t = *(const float4*)&g_part[sl][bm][rem];
        s.x += t.x; s.y += t.y; s.z += t.z; s.w += t.w;
    }
    float bias = (bm & 1) ? b2b[p] : b2a[p];
    s.x += bias; s.y += bias; s.z += bias; s.w += bias;
    float* out = ((bm & 1) ? g_b2 : g_a2) + (bm >> 1) * 65536 + rem;
    *(float4*)out = s;
}

// ---------------- kz: zero the e2n accumulator ----------------
__global__ void kz() {
    int i = blockIdx.x * blockDim.x + threadIdx.x;
    if (i < 8 * 256 * 8) g_np[i] = 0.f;
}

// ---------------- k3: e2n contraction ----------------
__global__ void __launch_bounds__(256) k3(const float* __restrict__ ew) {
    __shared__ float Bsm[256];
    __shared__ ull Esm[256 * 4];
    int b = blockIdx.x, pc = blockIdx.y, tid = threadIdx.x;
    ull a4[4] = {0ULL, 0ULL, 0ULL, 0ULL};
    for (int p = pc * 8; p < pc * 8 + 8; p++) {
        __syncthreads();
        Bsm[tid] = g_b2[(b * 256 + p) * 256 + tid];
        float e[8];
#pragma unroll
        for (int q = 0; q < 8; q++) e[q] = ew[q * 65536 + p * 256 + tid];
#pragma unroll
        for (int q = 0; q < 4; q++) Esm[tid * 4 + q] = pack2(e[2 * q], e[2 * q + 1]);
        __syncthreads();
        float ai = g_a2[(b * 256 + p) * 256 + tid];
#pragma unroll 4
        for (int j = 0; j < 256; j++) {
            float t = lrelu(ai + Bsm[j]);
            ull ts = pack2(t, t);
            const ull* er = &Esm[j * 4];
            a4[0] = ffma2(er[0], ts, a4[0]);
            a4[1] = ffma2(er[1], ts, a4[1]);
            a4[2] = ffma2(er[2], ts, a4[2]);
            a4[3] = ffma2(er[3], ts, a4[3]);
        }
    }
    float* dst = &g_np[b * 2048 + tid * 8];
#pragma unroll
    for (int q = 0; q < 4; q++) {
        float2 f = unpk(a4[q]);
        atomicAdd(dst + 2 * q, f.x);
        atomicAdd(dst + 2 * q + 1, f.y);
    }
}

// ---------------- k4: GCN / pooling / readout / MLP tail ----------------
__global__ void __launch_bounds__(256) k4(const float* __restrict__ x, const float* __restrict__ e2n_b,
    const float* __restrict__ a11_w, const float* __restrict__ a11_b,
    const float* __restrict__ a12_w, const float* __restrict__ a12_b,
    const float* __restrict__ g1_w,  const float* __restrict__ g1_b,
    const float* __restrict__ a21_w, const float* __restrict__ a21_b,
    const float* __restrict__ a22_w, const float* __restrict__ a22_b,
    const float* __restrict__ d1_w,  const float* __restrict__ d1_b,
    const float* __restrict__ d2_w,  const float* __restrict__ d2_b,
    const float* __restrict__ d3_w,  const float* __restrict__ d3_b,
    float* __restrict__ out) {
    __shared__ uint  m0[256][8];
    __shared__ float nod[256][8];
    __shared__ float dg0[256];
    __shared__ float tp[256];
    __shared__ float sc[256];
    __shared__ float t8[256][8];
    __shared__ int   sel[128];
    __shared__ float hg[128][8];
    __shared__ float on[128][8];
    __shared__ uint  m1[128][4];
    __shared__ float dg1[128];
    __shared__ float z[16];
    __shared__ float z1[128];
    __shared__ float z2[64];

    int b = blockIdx.x, t = threadIdx.x;
    const float* xb = x + b * 65536;

    {
        int d = 0;
#pragma unroll
        for (int w = 0; w < 8; w++) {
            uint u = 0;
            for (int l = 0; l < 32; l++)
                if (xb[t * 256 + w * 32 + l] > 0.f) u |= (1u << l);
            m0[t][w] = u; d += __popc(u);
        }
        dg0[t] = (float)d;
#pragma unroll
        for (int f = 0; f < 8; f++) nod[t][f] = lrelu(g_np[b * 2048 + t * 8 + f] + e2n_b[f]);
    }
    __syncthreads();
    {
        float s = 0;
#pragma unroll
        for (int f = 0; f < 8; f++) s += nod[t][f] * a11_w[f];
        tp[t] = s / dg0[t];
    }
    __syncthreads();
    {
        float s = 0;
        for (int j = 0; j < 256; j++) if ((m0[t][j >> 5] >> (j & 31)) & 1) s += tp[j];
        sc[t] = lrelu(s + a11_b[0]);
    }
    __syncthreads();
    tp[t] = sc[t] * a12_w[0] / dg0[t];
    __syncthreads();
    {
        float s = 0;
        for (int j = 0; j < 256; j++) if ((m0[t][j >> 5] >> (j & 31)) & 1) s += tp[j];
        sc[t] = 1.f / (1.f + expf(-(s + a12_b[0])));
    }
    __syncthreads();
    {
        float my = sc[t]; int r = 0;
        for (int j = 0; j < 256; j++) {
            float vj = sc[j];
            r += (vj > my) || (vj == my && j < t);
        }
        if (r < 128) sel[r] = t;
    }
    __syncthreads();
    for (int idx = t; idx < 1024; idx += 256) {
        int r = idx >> 3, f = idx & 7; int i = sel[r];
        on[r][f] = nod[i][f] * (1.f + sc[i]);
    }
    if (t < 128) {
        int i = sel[t], d = 0;
#pragma unroll
        for (int w = 0; w < 4; w++) {
            uint u = 0;
            for (int l = 0; l < 32; l++) {
                int j = sel[w * 32 + l];
                u |= ((m0[i][j >> 5] >> (j & 31)) & 1u) << l;
            }
            m1[t][w] = u; d += __popc(u);
        }
        dg1[t] = (float)d;
    }
    __syncthreads();
    if (t < 8) {
        float mx = -1e30f, sm = 0;
        for (int r = 0; r < 128; r++) { float v = on[r][t]; mx = fmaxf(mx, v); sm += v; }
        z[t] = mx; z[8 + t] = sm * (1.f / 128.f);
    }
    __syncthreads();
    for (int idx = t; idx < 1024; idx += 256) {
        int r2 = idx >> 3, fo = idx & 7;
        float s = 0;
#pragma unroll
        for (int f = 0; f < 8; f++) s += on[r2][f] * g1_w[fo * 8 + f];
        t8[r2][fo] = s / dg1[r2];
    }
    __syncthreads();
    for (int idx = t; idx < 1024; idx += 256) {
        int r = idx >> 3, fo = idx & 7;
        float s = 0;
        for (int j = 0; j < 128; j++) if ((m1[r][j >> 5] >> (j & 31)) & 1) s += t8[j][fo];
        hg[r][fo] = s + g1_b[fo];
    }
    __syncthreads();
    if (t < 128) {
        float s = 0;
#pragma unroll
        for (int f = 0; f < 8; f++) s += hg[t][f] * a21_w[f];
        tp[t] = s / dg1[t];
    }
    __syncthreads();
    if (t < 128) {
        float s = 0;
        for (int j = 0; j < 128; j++) if ((m1[t][j >> 5] >> (j & 31)) & 1) s += tp[j];
        sc[t] = lrelu(s + a21_b[0]);
    }
    __syncthreads();
    if (t < 128) tp[t] = sc[t] * a22_w[0] / dg1[t];
    __syncthreads();
    if (t < 128) {
        float s = 0;
        for (int j = 0; j < 128; j++) if ((m1[t][j >> 5] >> (j & 31)) & 1) s += tp[j];
        sc[t] = 1.f / (1.f + expf(-(s + a22_b[0])));
    }
    __syncthreads();
    if (t < 128) {
        float my = sc[t]; int r = 0;
        for (int j = 0; j < 128; j++) {
            float vj = sc[j];
            r += (vj > my) || (vj == my && j < t);
        }
        if (r < 64) sel[r] = t;
    }
    __syncthreads();
    for (int idx = t; idx < 512; idx += 256) {
        int r = idx >> 3, f = idx & 7; int i = sel[r];
        on[r][f] = hg[i][f] * (1.f + sc[i]);
    }
    __syncthreads();
    if (t < 8) {
        float mx = -1e30f, sm = 0;
        for (int r = 0; r < 64; r++) { float v = on[r][t]; mx = fmaxf(mx, v); sm += v; }
        z[t] += mx; z[8 + t] += sm * (1.f / 64.f);
    }
    __syncthreads();
    if (t < 128) {
        float s = d1_b[t];
#pragma unroll
        for (int f = 0; f < 16; f++) s += z[f] * d1_w[t * 16 + f];
        z1[t] = lrelu(s);
    }
    __syncthreads();
    if (t < 64) {
        float s = d2_b[t];
        for (int f = 0; f < 128; f++) s += z1[f] * d2_w[t * 128 + f];
        z2[t] = lrelu(s);
    }
    __syncthreads();
    if (t == 0) {
        float s = d3_b[0];
        for (int f = 0; f < 64; f++) s += z2[f] * d3_w[f];
        out[b] = s;
    }
}

// ---------------- launcher ----------------
extern "C" void kernel_launch(void* const* d_in, const int* in_sizes, int n_in,
                              void* d_out, int out_size) {
    const float* x    = (const float*)d_in[0];
    const float* w1a  = (const float*)d_in[1];
    const float* b1a  = (const float*)d_in[2];
    const float* w1b  = (const float*)d_in[3];
    const float* b1b  = (const float*)d_in[4];
    const float* w2a  = (const float*)d_in[5];
    const float* b2a  = (const float*)d_in[6];
    const float* w2b  = (const float*)d_in[7];
    const float* b2b  = (const float*)d_in[8];
    const float* e2nw = (const float*)d_in[9];
    const float* e2nb = (const float*)d_in[10];
    const float* a11w = (const float*)d_in[11];
    const float* a11b = (const float*)d_in[12];
    const float* a12w = (const float*)d_in[13];
    const float* a12b = (const float*)d_in[14];
    const float* g1w  = (const float*)d_in[15];
    const float* g1b  = (const float*)d_in[16];
    const float* a21w = (const float*)d_in[17];
    const float* a21b = (const float*)d_in[18];
    const float* a22w = (const float*)d_in[19];
    const float* a22b = (const float*)d_in[20];
    const float* d1w  = (const float*)d_in[21];
    const float* d1b  = (const float*)d_in[22];
    const float* d2w  = (const float*)d_in[23];
    const float* d2b  = (const float*)d_in[24];
    const float* d3w  = (const float*)d_in[25];
    const float* d3b  = (const float*)d_in[26];

    const int k2_smem = 2 * 64 * 128 * (int)sizeof(float);  // 65536 B
    cudaFuncSetAttribute(k2, cudaFuncAttributeMaxDynamicSharedMemorySize, k2_smem);

    k1<<<dim3(8, 128), 256>>>(x, w1a, b1a, w1b, b1b);
    kz<<<16, 1024>>>();
    k2<<<dim3(4, 8, 16), 256, k2_smem>>>(w2a, w2b);
    kr<<<1024, 256>>>(b2a, b2b);
    k3<<<dim3(8, 32), 256>>>(e2nw);
    k4<<<8, 256>>>(x, e2nb, a11w, a11b, a12w, a12b, g1w, g1b, a21w, a21b,
                   a22w, a22b, d1w, d1b, d2w, d2b, d3w, d3b, (float*)d_out);
}

// round 8
// speedup vs baseline: 2.9792x; 1.9606x over previous
#include <cuda_runtime.h>
#include <math.h>

typedef unsigned long long ull;
typedef unsigned int uint;
#define DV __device__ __forceinline__

// ---------------- scratch (device globals; no allocations) ----------------
__device__ float g_a1[8 * 128 * 256];
__device__ float g_b1[8 * 128 * 256];
__device__ float g_a2[8 * 256 * 256];
__device__ float g_b2[8 * 256 * 256];
__device__ float g_np[8 * 256 * 8];
__device__ float2 g_svi[2][8 * 128 * 256];  // [mode][(b*128+c)*256+k] = {sorted v, idx bits}
__device__ float2 g_uk[2][8 * 128 * 256];   // [mode][(b*128+c)*256+i] = {u, k bits}

DV float lrelu(float x) { return x > 0.f ? x : 0.33f * x; }
DV ull ffma2(ull a, ull b, ull c) {
    ull d; asm("fma.rn.f32x2 %0,%1,%2,%3;" : "=l"(d) : "l"(a), "l"(b), "l"(c)); return d;
}
DV ull pack2(float x, float y) {
    ull d; asm("mov.b64 %0,{%1,%2};" : "=l"(d) : "r"(__float_as_uint(x)), "r"(__float_as_uint(y))); return d;
}
DV float2 unpk(ull v) {
    float2 f; asm("mov.b64 {%0,%1},%2;" : "=f"(f.x), "=f"(f.y) : "l"(v)); return f;
}

// ---------------- k1: layer-1 rank terms ----------------
// a1[b,c,i] = sum_j x[b,i,j]*w1a[c,j] + b1a[c] ; b1[b,c,j] = sum_i x[b,i,j]*w1b[c,i] + b1b[c]
__global__ void __launch_bounds__(256) k1(const float* __restrict__ x,
                                          const float* __restrict__ w1a, const float* __restrict__ b1a,
                                          const float* __restrict__ w1b, const float* __restrict__ b1b) {
    __shared__ float wa[256], wb[256];
    int b = blockIdx.x, c = blockIdx.y, t = threadIdx.x;
    wa[t] = w1a[c * 256 + t];
    wb[t] = w1b[c * 256 + t];
    __syncthreads();
    const float* xb = x + b * 65536;
    float aA = 0.f, aB = 0.f;
    const float4* xr = (const float4*)(xb + t * 256);
#pragma unroll 8
    for (int j4 = 0; j4 < 64; j4++) {
        float4 v = xr[j4];
        aA += v.x * wa[j4 * 4] + v.y * wa[j4 * 4 + 1] + v.z * wa[j4 * 4 + 2] + v.w * wa[j4 * 4 + 3];
    }
#pragma unroll 8
    for (int i = 0; i < 256; i++) aB += xb[i * 256 + t] * wb[i];
    g_a1[(b * 128 + c) * 256 + t] = aA + b1a[c];
    g_b1[(b * 128 + c) * 256 + t] = aB + b1b[c];
}

// ---------------- ks: per-(b,c) bitonic sort of v-array + per-i thresholds ----------------
// mode0 (produces a2): v = b1 (summed), u = a1 (free index)
// mode1 (produces b2): v = a1 (summed), u = b1 (free index)
__global__ void __launch_bounds__(256) ks() {
    __shared__ float sv[256];
    __shared__ int si[256];
    int b = blockIdx.x, c = blockIdx.y, t = threadIdx.x;
    int base = (b * 128 + c) * 256;
    for (int mode = 0; mode < 2; mode++) {
        const float* varr = mode ? g_a1 : g_b1;
        const float* uarr = mode ? g_b1 : g_a1;
        sv[t] = varr[base + t];
        si[t] = t;
        __syncthreads();
        for (int k = 2; k <= 256; k <<= 1) {
            for (int j = k >> 1; j > 0; j >>= 1) {
                int ixj = t ^ j;
                if (ixj > t) {
                    bool up = ((t & k) == 0);
                    float v0 = sv[t], v1 = sv[ixj];
                    if ((v0 > v1) == up) {
                        int i0 = si[t], i1 = si[ixj];
                        sv[t] = v1; sv[ixj] = v0;
                        si[t] = i1; si[ixj] = i0;
                    }
                }
                __syncthreads();
            }
        }
        g_svi[mode][base + t] = make_float2(sv[t], __int_as_float(si[t]));
        // threshold: k_i = #{ sorted v <= -u_i }  (active suffix = v > -u_i)
        float u = uarr[base + t];
        float nu = -u;
        int lo = 0, hi = 256;
#pragma unroll
        for (int it = 0; it < 8; it++) {
            int mid = (lo + hi) >> 1;
            if (sv[mid] <= nu) lo = mid + 1; else hi = mid;
        }
        g_uk[mode][base + t] = make_float2(u, __int_as_float(lo));
        __syncthreads();
    }
}

// ---------------- kz: zero the e2n accumulator ----------------
__global__ void kz() { g_np[blockIdx.x * 1024 + threadIdx.x] = 0.f; }

// ---------------- k2s: layer-2 via sorted suffix sums ----------------
// out[p,i] = sum_c { 0.33*(u_i*SW[0]+SWV[0]) + 0.67*(u_i*SW[k_i]+SWV[k_i]) } + bias[p]
// SW[k]  = suffix sum over sorted order of w[p,c,sigma(k')]
// SWV[k] = suffix sum of w*v
__global__ void __launch_bounds__(256) k2s(const float* __restrict__ w2a, const float* __restrict__ b2a,
                                           const float* __restrict__ w2b, const float* __restrict__ b2b) {
    extern __shared__ char smem_raw[];
    float2* SWp = (float2*)smem_raw;        // [257][33]
    float2* svi = SWp + 257 * 33;           // [256]
    float2* uk = svi + 256;                 // [256]
    float2* segtot = uk + 256;              // [8][32]
    float* wtmp = (float*)(segtot + 256);   // [256][33]

    int t = threadIdx.x;
    int p0 = blockIdx.x * 32;
    int bm = blockIdx.y, b = bm >> 1, mode = bm & 1;
    const float* W = mode ? w2b : w2a;
    const float* bias = mode ? b2b : b2a;
    const float2* gsvi = g_svi[mode] + b * 32768;
    const float2* guk = g_uk[mode] + b * 32768;
    float* outp = (mode ? g_b2 : g_a2) + b * 65536;

    int p = t & 31, seg = t >> 5;
    int wlp = t >> 3, wls = t & 7;

    float acc[32];
#pragma unroll
    for (int m = 0; m < 32; m++) acc[m] = 0.f;

    for (int c = 0; c < 128; c++) {
        __syncthreads();
        svi[t] = gsvi[c * 256 + t];
        uk[t] = guk[c * 256 + t];
        const float* wrow = W + (size_t)(p0 + wlp) * 32768 + c * 256;
#pragma unroll
        for (int m = 0; m < 8; m++) {
            int q = wls + 8 * m;
            float4 f = *(const float4*)(wrow + 4 * q);
            wtmp[(4 * q + 0) * 33 + wlp] = f.x;
            wtmp[(4 * q + 1) * 33 + wlp] = f.y;
            wtmp[(4 * q + 2) * 33 + wlp] = f.z;
            wtmp[(4 * q + 3) * 33 + wlp] = f.w;
        }
        if (t < 32) SWp[256 * 33 + t] = make_float2(0.f, 0.f);  // k=256 -> empty suffix
        __syncthreads();
        // local backward suffix scan within 32-segment
        float run = 0.f, runv = 0.f;
#pragma unroll
        for (int q = 31; q >= 0; q--) {
            int kk = seg * 32 + q;
            float2 sva = svi[kk];
            float wv = wtmp[__float_as_int(sva.y) * 33 + p];
            run += wv;
            runv = fmaf(wv, sva.x, runv);
            SWp[kk * 33 + p] = make_float2(run, runv);
        }
        segtot[seg * 32 + p] = make_float2(run, runv);
        __syncthreads();
        float offw = 0.f, offv = 0.f;
        for (int s2 = seg + 1; s2 < 8; s2++) {
            float2 st = segtot[s2 * 32 + p];
            offw += st.x; offv += st.y;
        }
#pragma unroll
        for (int q = 0; q < 32; q++) {
            int kk = seg * 32 + q;
            float2 cur = SWp[kk * 33 + p];
            SWp[kk * 33 + p] = make_float2(cur.x + offw, cur.y + offv);
        }
        __syncthreads();
        // main: 4 FMA + 2 LDS.64 per (p,i)
        float2 SW0 = SWp[p];
#pragma unroll 4
        for (int m = 0; m < 32; m++) {
            int i = seg * 32 + m;
            float2 ukv = uk[i];
            int ki = __float_as_int(ukv.y);
            float2 s2 = SWp[ki * 33 + p];
            float t1 = fmaf(ukv.x, s2.x, s2.y);
            float t0 = fmaf(ukv.x, SW0.x, SW0.y);
            acc[m] = fmaf(0.33f, t0, fmaf(1.0f - 0.33f, t1, acc[m]));
        }
    }
    float bs = bias[p0 + p];
    float* dst = outp + (size_t)(p0 + p) * 256 + seg * 32;
#pragma unroll
    for (int m = 0; m < 32; m += 4) {
        float4 o = make_float4(acc[m] + bs, acc[m + 1] + bs, acc[m + 2] + bs, acc[m + 3] + bs);
        *(float4*)(dst + m) = o;
    }
}

// ---------------- k3: e2n contraction ----------------
__global__ void __launch_bounds__(256) k3(const float* __restrict__ ew) {
    __shared__ float Bsm[256];
    __shared__ ull Esm[256 * 4];
    int b = blockIdx.x, pc = blockIdx.y, tid = threadIdx.x;
    ull a4[4] = {0ULL, 0ULL, 0ULL, 0ULL};
    for (int p = pc * 4; p < pc * 4 + 4; p++) {
        __syncthreads();
        Bsm[tid] = g_b2[(b * 256 + p) * 256 + tid];
        float e[8];
#pragma unroll
        for (int q = 0; q < 8; q++) e[q] = ew[q * 65536 + p * 256 + tid];
#pragma unroll
        for (int q = 0; q < 4; q++) Esm[tid * 4 + q] = pack2(e[2 * q], e[2 * q + 1]);
        __syncthreads();
        float ai = g_a2[(b * 256 + p) * 256 + tid];
#pragma unroll 4
        for (int j = 0; j < 256; j++) {
            float t = lrelu(ai + Bsm[j]);
            ull ts = pack2(t, t);
            const ull* er = &Esm[j * 4];
            a4[0] = ffma2(er[0], ts, a4[0]);
            a4[1] = ffma2(er[1], ts, a4[1]);
            a4[2] = ffma2(er[2], ts, a4[2]);
            a4[3] = ffma2(er[3], ts, a4[3]);
        }
    }
    float* dst = &g_np[b * 2048 + tid * 8];
#pragma unroll
    for (int q = 0; q < 4; q++) {
        float2 f = unpk(a4[q]);
        atomicAdd(dst + 2 * q, f.x);
        atomicAdd(dst + 2 * q + 1, f.y);
    }
}

// ---------------- k4: GCN / pooling / readout / MLP tail ----------------
__global__ void __launch_bounds__(256) k4(const float* __restrict__ x, const float* __restrict__ e2n_b,
    const float* __restrict__ a11_w, const float* __restrict__ a11_b,
    const float* __restrict__ a12_w, const float* __restrict__ a12_b,
    const float* __restrict__ g1_w,  const float* __restrict__ g1_b,
    const float* __restrict__ a21_w, const float* __restrict__ a21_b,
    const float* __restrict__ a22_w, const float* __restrict__ a22_b,
    const float* __restrict__ d1_w,  const float* __restrict__ d1_b,
    const float* __restrict__ d2_w,  const float* __restrict__ d2_b,
    const float* __restrict__ d3_w,  const float* __restrict__ d3_b,
    float* __restrict__ out) {
    __shared__ uint  m0[256][8];
    __shared__ float nod[256][8];
    __shared__ float dg0[256];
    __shared__ float tp[256];
    __shared__ float sc[256];
    __shared__ float t8[256][8];
    __shared__ int   sel[128];
    __shared__ float hg[128][8];
    __shared__ float on[128][8];
    __shared__ uint  m1[128][4];
    __shared__ float dg1[128];
    __shared__ float z[16];
    __shared__ float z1[128];
    __shared__ float z2[64];

    int b = blockIdx.x, t = threadIdx.x;
    const float* xb = x + b * 65536;
    {
        int d = 0;
#pragma unroll
        for (int w = 0; w < 8; w++) {
            uint u = 0;
            for (int l = 0; l < 32; l++)
                if (xb[t * 256 + w * 32 + l] > 0.f) u |= (1u << l);
            m0[t][w] = u; d += __popc(u);
        }
        dg0[t] = (float)d;
#pragma unroll
        for (int f = 0; f < 8; f++) nod[t][f] = lrelu(g_np[b * 2048 + t * 8 + f] + e2n_b[f]);
    }
    __syncthreads();
    {
        float s = 0;
#pragma unroll
        for (int f = 0; f < 8; f++) s += nod[t][f] * a11_w[f];
        tp[t] = s / dg0[t];
    }
    __syncthreads();
    {
        float s = 0;
        for (int j = 0; j < 256; j++) if ((m0[t][j >> 5] >> (j & 31)) & 1) s += tp[j];
        sc[t] = lrelu(s + a11_b[0]);
    }
    __syncthreads();
    tp[t] = sc[t] * a12_w[0] / dg0[t];
    __syncthreads();
    {
        float s = 0;
        for (int j = 0; j < 256; j++) if ((m0[t][j >> 5] >> (j & 31)) & 1) s += tp[j];
        sc[t] = 1.f / (1.f + expf(-(s + a12_b[0])));
    }
    __syncthreads();
    {
        float my = sc[t]; int r = 0;
        for (int j = 0; j < 256; j++) {
            float vj = sc[j];
            r += (vj > my) || (vj == my && j < t);
        }
        if (r < 128) sel[r] = t;
    }
    __syncthreads();
    for (int idx = t; idx < 1024; idx += 256) {
        int r = idx >> 3, f = idx & 7; int i = sel[r];
        on[r][f] = nod[i][f] * (1.f + sc[i]);
    }
    if (t < 128) {
        int i = sel[t], d = 0;
#pragma unroll
        for (int w = 0; w < 4; w++) {
            uint u = 0;
            for (int l = 0; l < 32; l++) {
                int j = sel[w * 32 + l];
                u |= ((m0[i][j >> 5] >> (j & 31)) & 1u) << l;
            }
            m1[t][w] = u; d += __popc(u);
        }
        dg1[t] = (float)d;
    }
    __syncthreads();
    if (t < 8) {
        float mx = -1e30f, sm = 0;
        for (int r = 0; r < 128; r++) { float v = on[r][t]; mx = fmaxf(mx, v); sm += v; }
        z[t] = mx; z[8 + t] = sm * (1.f / 128.f);
    }
    __syncthreads();
    for (int idx = t; idx < 1024; idx += 256) {
        int r2 = idx >> 3, fo = idx & 7;
        float s = 0;
#pragma unroll
        for (int f = 0; f < 8; f++) s += on[r2][f] * g1_w[fo * 8 + f];
        t8[r2][fo] = s / dg1[r2];
    }
    __syncthreads();
    for (int idx = t; idx < 1024; idx += 256) {
        int r = idx >> 3, fo = idx & 7;
        float s = 0;
        for (int j = 0; j < 128; j++) if ((m1[r][j >> 5] >> (j & 31)) & 1) s += t8[j][fo];
        hg[r][fo] = s + g1_b[fo];
    }
    __syncthreads();
    if (t < 128) {
        float s = 0;
#pragma unroll
        for (int f = 0; f < 8; f++) s += hg[t][f] * a21_w[f];
        tp[t] = s / dg1[t];
    }
    __syncthreads();
    if (t < 128) {
        float s = 0;
        for (int j = 0; j < 128; j++) if ((m1[t][j >> 5] >> (j & 31)) & 1) s += tp[j];
        sc[t] = lrelu(s + a21_b[0]);
    }
    __syncthreads();
    if (t < 128) tp[t] = sc[t] * a22_w[0] / dg1[t];
    __syncthreads();
    if (t < 128) {
        float s = 0;
        for (int j = 0; j < 128; j++) if ((m1[t][j >> 5] >> (j & 31)) & 1) s += tp[j];
        sc[t] = 1.f / (1.f + expf(-(s + a22_b[0])));
    }
    __syncthreads();
    if (t < 128) {
        float my = sc[t]; int r = 0;
        for (int j = 0; j < 128; j++) {
            float vj = sc[j];
            r += (vj > my) || (vj == my && j < t);
        }
        if (r < 64) sel[r] = t;
    }
    __syncthreads();
    for (int idx = t; idx < 512; idx += 256) {
        int r = idx >> 3, f = idx & 7; int i = sel[r];
        on[r][f] = hg[i][f] * (1.f + sc[i]);
    }
    __syncthreads();
    if (t < 8) {
        float mx = -1e30f, sm = 0;
        for (int r = 0; r < 64; r++) { float v = on[r][t]; mx = fmaxf(mx, v); sm += v; }
        z[t] += mx; z[8 + t] += sm * (1.f / 64.f);
    }
    __syncthreads();
    if (t < 128) {
        float s = d1_b[t];
#pragma unroll
        for (int f = 0; f < 16; f++) s += z[f] * d1_w[t * 16 + f];
        z1[t] = lrelu(s);
    }
    __syncthreads();
    if (t < 64) {
        float s = d2_b[t];
        for (int f = 0; f < 128; f++) s += z1[f] * d2_w[t * 128 + f];
        z2[t] = lrelu(s);
    }
    __syncthreads();
    if (t == 0) {
        float s = d3_b[0];
        for (int f = 0; f < 64; f++) s += z2[f] * d3_w[f];
        out[b] = s;
    }
}

// ---------------- launcher ----------------
extern "C" void kernel_launch(void* const* d_in, const int* in_sizes, int n_in,
                              void* d_out, int out_size) {
    const float* x    = (const float*)d_in[0];
    const float* w1a  = (const float*)d_in[1];
    const float* b1a  = (const float*)d_in[2];
    const float* w1b  = (const float*)d_in[3];
    const float* b1b  = (const float*)d_in[4];
    const float* w2a  = (const float*)d_in[5];
    const float* b2a  = (const float*)d_in[6];
    const float* w2b  = (const float*)d_in[7];
    const float* b2b  = (const float*)d_in[8];
    const float* e2nw = (const float*)d_in[9];
    const float* e2nb = (const float*)d_in[10];
    const float* a11w = (const float*)d_in[11];
    const float* a11b = (const float*)d_in[12];
    const float* a12w = (const float*)d_in[13];
    const float* a12b = (const float*)d_in[14];
    const float* g1w  = (const float*)d_in[15];
    const float* g1b  = (const float*)d_in[16];
    const float* a21w = (const float*)d_in[17];
    const float* a21b = (const float*)d_in[18];
    const float* a22w = (const float*)d_in[19];
    const float* a22b = (const float*)d_in[20];
    const float* d1w  = (const float*)d_in[21];
    const float* d1b  = (const float*)d_in[22];
    const float* d2w  = (const float*)d_in[23];
    const float* d2b  = (const float*)d_in[24];
    const float* d3w  = (const float*)d_in[25];
    const float* d3b  = (const float*)d_in[26];

    // dynamic smem for k2s: SWp 257*33*8 + svi 2048 + uk 2048 + segtot 2048 + wtmp 256*33*4
    const int k2s_smem = 257 * 33 * 8 + 2048 + 2048 + 2048 + 256 * 33 * 4;  // 107,784 B
    cudaFuncSetAttribute(k2s, cudaFuncAttributeMaxDynamicSharedMemorySize, k2s_smem);

    k1<<<dim3(8, 128), 256>>>(x, w1a, b1a, w1b, b1b);
    ks<<<dim3(8, 128), 256>>>();
    kz<<<16, 1024>>>();
    k2s<<<dim3(8, 16), 256, k2s_smem>>>(w2a, b2a, w2b, b2b);   // 4th launch -> profiled
    k3<<<dim3(8, 64), 256>>>(e2nw);
    k4<<<8, 256>>>(x, e2nb, a11w, a11b, a12w, a12b, g1w, g1b, a21w, a21b,
                   a22w, a22b, d1w, d1b, d2w, d2b, d3w, d3b, (float*)d_out);
}

// round 9
// speedup vs baseline: 4.5603x; 1.5307x over previous
#include <cuda_runtime.h>
#include <math.h>

typedef unsigned long long ull;
typedef unsigned int uint;
#define DV __device__ __forceinline__

// ---------------- scratch (device globals; no allocations) ----------------
__device__ float g_a1[8 * 128 * 256];
__device__ float g_b1[8 * 128 * 256];
__device__ float g_a2[8 * 256 * 256];
__device__ float g_b2[8 * 256 * 256];
__device__ float g_np[8 * 256 * 8];
__device__ float2 g_svi[2][8 * 128 * 256];  // [mode][(b*128+c)*256+k] = {sorted v, idx bits}
__device__ float2 g_uk[2][8 * 128 * 256];   // [mode][(b*128+c)*256+i] = {u, k bits}

DV float lrelu(float x) { return x > 0.f ? x : 0.33f * x; }
DV ull ffma2(ull a, ull b, ull c) {
    ull d; asm("fma.rn.f32x2 %0,%1,%2,%3;" : "=l"(d) : "l"(a), "l"(b), "l"(c)); return d;
}
DV ull pack2(float x, float y) {
    ull d; asm("mov.b64 %0,{%1,%2};" : "=l"(d) : "r"(__float_as_uint(x)), "r"(__float_as_uint(y))); return d;
}
DV float2 unpk(ull v) {
    float2 f; asm("mov.b64 {%0,%1},%2;" : "=f"(f.x), "=f"(f.y) : "l"(v)); return f;
}

// ---------------- k1: layer-1 rank terms ----------------
__global__ void __launch_bounds__(256) k1(const float* __restrict__ x,
                                          const float* __restrict__ w1a, const float* __restrict__ b1a,
                                          const float* __restrict__ w1b, const float* __restrict__ b1b) {
    __shared__ float wa[256], wb[256];
    int b = blockIdx.x, c = blockIdx.y, t = threadIdx.x;
    wa[t] = w1a[c * 256 + t];
    wb[t] = w1b[c * 256 + t];
    __syncthreads();
    const float* xb = x + b * 65536;
    float aA = 0.f, aB = 0.f;
    const float4* xr = (const float4*)(xb + t * 256);
#pragma unroll 8
    for (int j4 = 0; j4 < 64; j4++) {
        float4 v = xr[j4];
        aA += v.x * wa[j4 * 4] + v.y * wa[j4 * 4 + 1] + v.z * wa[j4 * 4 + 2] + v.w * wa[j4 * 4 + 3];
    }
#pragma unroll 8
    for (int i = 0; i < 256; i++) aB += xb[i * 256 + t] * wb[i];
    g_a1[(b * 128 + c) * 256 + t] = aA + b1a[c];
    g_b1[(b * 128 + c) * 256 + t] = aB + b1b[c];
}

// ---------------- ks: per-(b,c) bitonic sort of v-array + per-i thresholds ----------------
__global__ void __launch_bounds__(256) ks() {
    __shared__ float sv[256];
    __shared__ int si[256];
    int b = blockIdx.x, c = blockIdx.y, t = threadIdx.x;
    int base = (b * 128 + c) * 256;
    for (int mode = 0; mode < 2; mode++) {
        const float* varr = mode ? g_a1 : g_b1;
        const float* uarr = mode ? g_b1 : g_a1;
        sv[t] = varr[base + t];
        si[t] = t;
        __syncthreads();
        for (int k = 2; k <= 256; k <<= 1) {
            for (int j = k >> 1; j > 0; j >>= 1) {
                int ixj = t ^ j;
                if (ixj > t) {
                    bool up = ((t & k) == 0);
                    float v0 = sv[t], v1 = sv[ixj];
                    if ((v0 > v1) == up) {
                        int i0 = si[t], i1 = si[ixj];
                        sv[t] = v1; sv[ixj] = v0;
                        si[t] = i1; si[ixj] = i0;
                    }
                }
                __syncthreads();
            }
        }
        g_svi[mode][base + t] = make_float2(sv[t], __int_as_float(si[t]));
        float u = uarr[base + t];
        float nu = -u;
        int lo = 0, hi = 256;
#pragma unroll
        for (int it = 0; it < 8; it++) {
            int mid = (lo + hi) >> 1;
            if (sv[mid] <= nu) lo = mid + 1; else hi = mid;
        }
        g_uk[mode][base + t] = make_float2(u, __int_as_float(lo));
        __syncthreads();
    }
}

// ---------------- kz: zero the e2n accumulator ----------------
__global__ void kz() { g_np[blockIdx.x * 1024 + threadIdx.x] = 0.f; }

// ---------------- k2s: layer-2 via sorted suffix sums (16-p tiles, reg-batched scan) ----------------
// Bit-identical math to R8 version: same 8x32 seg scan order, same offset order, same c order.
__global__ void __launch_bounds__(128, 3) k2s(const float* __restrict__ w2a, const float* __restrict__ b2a,
                                              const float* __restrict__ w2b, const float* __restrict__ b2b) {
    extern __shared__ char smem_raw[];
    float2* SWp = (float2*)smem_raw;        // [257][17] raw (pre-offset) suffix pairs
    float2* svi = SWp + 257 * 17;           // [256]
    float2* uk = svi + 256;                 // [256]
    float2* segtot = uk + 256;              // [8][16]
    float2* OS = segtot + 8 * 16;           // [9][16] per-seg offsets (row 8 = zeros)
    float* wtmp = (float*)(OS + 9 * 16);    // [256][17]

    int t = threadIdx.x;
    int p0 = blockIdx.x * 16;
    int bm = blockIdx.y, b = bm >> 1, mode = bm & 1;
    const float* W = mode ? w2b : w2a;
    const float* bias = mode ? b2b : b2a;
    const float2* gsvi = g_svi[mode] + b * 32768;
    const float2* guk = g_uk[mode] + b * 32768;
    float* outp = (mode ? g_b2 : g_a2) + b * 65536;

    int p = t & 15, seg = t >> 4;       // scan/main mapping (8 segs x 32 k)
    int wlp = t >> 3, wls = t & 7;      // W loader mapping (16 p rows)

    // one-time zero rows (k=256 empty suffix; OS row 8)
    if (t < 16) {
        SWp[256 * 17 + t] = make_float2(0.f, 0.f);
        OS[8 * 16 + t] = make_float2(0.f, 0.f);
    }

    float acc[32];
#pragma unroll
    for (int m = 0; m < 32; m++) acc[m] = 0.f;

    const float* wbase = W + (size_t)(p0 + wlp) * 32768;

    for (int c = 0; c < 128; c++) {
        __syncthreads();
        svi[t] = gsvi[c * 256 + t];
        svi[t + 128] = gsvi[c * 256 + t + 128];
        uk[t] = guk[c * 256 + t];
        uk[t + 128] = guk[c * 256 + t + 128];
        const float* wrow = wbase + c * 256;
#pragma unroll
        for (int m = 0; m < 8; m++) {
            int q = wls + 8 * m;
            float4 f = *(const float4*)(wrow + 4 * q);
            wtmp[(4 * q + 0) * 17 + wlp] = f.x;
            wtmp[(4 * q + 1) * 17 + wlp] = f.y;
            wtmp[(4 * q + 2) * 17 + wlp] = f.z;
            wtmp[(4 * q + 3) * 17 + wlp] = f.w;
        }
        __syncthreads();
        // backward suffix scan within this thread's 32-k segment (q = 31..0),
        // register-batched in groups of 8 to pipeline the dependent LDS pair.
        float run = 0.f, runv = 0.f;
#pragma unroll
        for (int batch = 3; batch >= 0; batch--) {
            float2 sv8[8];
            float wv8[8];
#pragma unroll
            for (int e = 7; e >= 0; e--) sv8[e] = svi[seg * 32 + batch * 8 + e];
#pragma unroll
            for (int e = 7; e >= 0; e--) wv8[e] = wtmp[__float_as_int(sv8[e].y) * 17 + p];
#pragma unroll
            for (int e = 7; e >= 0; e--) {
                int kk = seg * 32 + batch * 8 + e;
                run += wv8[e];
                runv = fmaf(wv8[e], sv8[e].x, runv);
                SWp[kk * 17 + p] = make_float2(run, runv);
            }
        }
        segtot[seg * 16 + p] = make_float2(run, runv);
        __syncthreads();
        // per-seg offset (ascending s2 order, identical to previous version)
        {
            float offw = 0.f, offv = 0.f;
            for (int s2 = seg + 1; s2 < 8; s2++) {
                float2 st = segtot[s2 * 16 + p];
                offw += st.x; offv += st.y;
            }
            OS[seg * 16 + p] = make_float2(offw, offv);
        }
        __syncthreads();
        // main: apply offset at gather time (same fadds as the old update pass)
        float2 sw0r = SWp[p];
        float2 os0 = OS[p];
        float sw0x = sw0r.x + os0.x, sw0y = sw0r.y + os0.y;
#pragma unroll 4
        for (int m = 0; m < 32; m++) {
            int i = seg * 32 + m;
            float2 ukv = uk[i];
            int ki = __float_as_int(ukv.y);
            float2 s2 = SWp[ki * 17 + p];
            float2 os = OS[(ki >> 5) * 16 + p];
            float t1 = fmaf(ukv.x, s2.x + os.x, s2.y + os.y);
            float t0 = fmaf(ukv.x, sw0x, sw0y);
            acc[m] = fmaf(0.33f, t0, fmaf(1.0f - 0.33f, t1, acc[m]));
        }
    }
    float bs = bias[p0 + p];
    float* dst = outp + (size_t)(p0 + p) * 256 + seg * 32;
#pragma unroll
    for (int m = 0; m < 32; m += 4) {
        float4 o = make_float4(acc[m] + bs, acc[m + 1] + bs, acc[m + 2] + bs, acc[m + 3] + bs);
        *(float4*)(dst + m) = o;
    }
}

// ---------------- k3: e2n contraction ----------------
__global__ void __launch_bounds__(256) k3(const float* __restrict__ ew) {
    __shared__ float Bsm[256];
    __shared__ ull Esm[256 * 4];
    int b = blockIdx.x, pc = blockIdx.y, tid = threadIdx.x;
    ull a4[4] = {0ULL, 0ULL, 0ULL, 0ULL};
    for (int p = pc * 4; p < pc * 4 + 4; p++) {
        __syncthreads();
        Bsm[tid] = g_b2[(b * 256 + p) * 256 + tid];
        float e[8];
#pragma unroll
        for (int q = 0; q < 8; q++) e[q] = ew[q * 65536 + p * 256 + tid];
#pragma unroll
        for (int q = 0; q < 4; q++) Esm[tid * 4 + q] = pack2(e[2 * q], e[2 * q + 1]);
        __syncthreads();
        float ai = g_a2[(b * 256 + p) * 256 + tid];
#pragma unroll 4
        for (int j = 0; j < 256; j++) {
            float t = lrelu(ai + Bsm[j]);
            ull ts = pack2(t, t);
            const ull* er = &Esm[j * 4];
            a4[0] = ffma2(er[0], ts, a4[0]);
            a4[1] = ffma2(er[1], ts, a4[1]);
            a4[2] = ffma2(er[2], ts, a4[2]);
            a4[3] = ffma2(er[3], ts, a4[3]);
        }
    }
    float* dst = &g_np[b * 2048 + tid * 8];
#pragma unroll
    for (int q = 0; q < 4; q++) {
        float2 f = unpk(a4[q]);
        atomicAdd(dst + 2 * q, f.x);
        atomicAdd(dst + 2 * q + 1, f.y);
    }
}

// ---------------- k4: GCN / pooling / readout / MLP tail ----------------
__global__ void __launch_bounds__(256) k4(const float* __restrict__ x, const float* __restrict__ e2n_b,
    const float* __restrict__ a11_w, const float* __restrict__ a11_b,
    const float* __restrict__ a12_w, const float* __restrict__ a12_b,
    const float* __restrict__ g1_w,  const float* __restrict__ g1_b,
    const float* __restrict__ a21_w, const float* __restrict__ a21_b,
    const float* __restrict__ a22_w, const float* __restrict__ a22_b,
    const float* __restrict__ d1_w,  const float* __restrict__ d1_b,
    const float* __restrict__ d2_w,  const float* __restrict__ d2_b,
    const float* __restrict__ d3_w,  const float* __restrict__ d3_b,
    float* __restrict__ out) {
    __shared__ uint  m0[256][8];
    __shared__ float nod[256][8];
    __shared__ float dg0[256];
    __shared__ float tp[256];
    __shared__ float sc[256];
    __shared__ float t8[256][8];
    __shared__ int   sel[128];
    __shared__ float hg[128][8];
    __shared__ float on[128][8];
    __shared__ uint  m1[128][4];
    __shared__ float dg1[128];
    __shared__ float z[16];
    __shared__ float z1[128];
    __shared__ float z2[64];

    int b = blockIdx.x, t = threadIdx.x;
    const float* xb = x + b * 65536;
    {
        int d = 0;
#pragma unroll
        for (int w = 0; w < 8; w++) {
            uint u = 0;
            for (int l = 0; l < 32; l++)
                if (xb[t * 256 + w * 32 + l] > 0.f) u |= (1u << l);
            m0[t][w] = u; d += __popc(u);
        }
        dg0[t] = (float)d;
#pragma unroll
        for (int f = 0; f < 8; f++) nod[t][f] = lrelu(g_np[b * 2048 + t * 8 + f] + e2n_b[f]);
    }
    __syncthreads();
    {
        float s = 0;
#pragma unroll
        for (int f = 0; f < 8; f++) s += nod[t][f] * a11_w[f];
        tp[t] = s / dg0[t];
    }
    __syncthreads();
    {
        float s = 0;
        for (int j = 0; j < 256; j++) if ((m0[t][j >> 5] >> (j & 31)) & 1) s += tp[j];
        sc[t] = lrelu(s + a11_b[0]);
    }
    __syncthreads();
    tp[t] = sc[t] * a12_w[0] / dg0[t];
    __syncthreads();
    {
        float s = 0;
        for (int j = 0; j < 256; j++) if ((m0[t][j >> 5] >> (j & 31)) & 1) s += tp[j];
        sc[t] = 1.f / (1.f + expf(-(s + a12_b[0])));
    }
    __syncthreads();
    {
        float my = sc[t]; int r = 0;
        for (int j = 0; j < 256; j++) {
            float vj = sc[j];
            r += (vj > my) || (vj == my && j < t);
        }
        if (r < 128) sel[r] = t;
    }
    __syncthreads();
    for (int idx = t; idx < 1024; idx += 256) {
        int r = idx >> 3, f = idx & 7; int i = sel[r];
        on[r][f] = nod[i][f] * (1.f + sc[i]);
    }
    if (t < 128) {
        int i = sel[t], d = 0;
#pragma unroll
        for (int w = 0; w < 4; w++) {
            uint u = 0;
            for (int l = 0; l < 32; l++) {
                int j = sel[w * 32 + l];
                u |= ((m0[i][j >> 5] >> (j & 31)) & 1u) << l;
            }
            m1[t][w] = u; d += __popc(u);
        }
        dg1[t] = (float)d;
    }
    __syncthreads();
    if (t < 8) {
        float mx = -1e30f, sm = 0;
        for (int r = 0; r < 128; r++) { float v = on[r][t]; mx = fmaxf(mx, v); sm += v; }
        z[t] = mx; z[8 + t] = sm * (1.f / 128.f);
    }
    __syncthreads();
    for (int idx = t; idx < 1024; idx += 256) {
        int r2 = idx >> 3, fo = idx & 7;
        float s = 0;
#pragma unroll
        for (int f = 0; f < 8; f++) s += on[r2][f] * g1_w[fo * 8 + f];
        t8[r2][fo] = s / dg1[r2];
    }
    __syncthreads();
    for (int idx = t; idx < 1024; idx += 256) {
        int r = idx >> 3, fo = idx & 7;
        float s = 0;
        for (int j = 0; j < 128; j++) if ((m1[r][j >> 5] >> (j & 31)) & 1) s += t8[j][fo];
        hg[r][fo] = s + g1_b[fo];
    }
    __syncthreads();
    if (t < 128) {
        float s = 0;
#pragma unroll
        for (int f = 0; f < 8; f++) s += hg[t][f] * a21_w[f];
        tp[t] = s / dg1[t];
    }
    __syncthreads();
    if (t < 128) {
        float s = 0;
        for (int j = 0; j < 128; j++) if ((m1[t][j >> 5] >> (j & 31)) & 1) s += tp[j];
        sc[t] = lrelu(s + a21_b[0]);
    }
    __syncthreads();
    if (t < 128) tp[t] = sc[t] * a22_w[0] / dg1[t];
    __syncthreads();
    if (t < 128) {
        float s = 0;
        for (int j = 0; j < 128; j++) if ((m1[t][j >> 5] >> (j & 31)) & 1) s += tp[j];
        sc[t] = 1.f / (1.f + expf(-(s + a22_b[0])));
    }
    __syncthreads();
    if (t < 128) {
        float my = sc[t]; int r = 0;
        for (int j = 0; j < 128; j++) {
            float vj = sc[j];
            r += (vj > my) || (vj == my && j < t);
        }
        if (r < 64) sel[r] = t;
    }
    __syncthreads();
    for (int idx = t; idx < 512; idx += 256) {
        int r = idx >> 3, f = idx & 7; int i = sel[r];
        on[r][f] = hg[i][f] * (1.f + sc[i]);
    }
    __syncthreads();
    if (t < 8) {
        float mx = -1e30f, sm = 0;
        for (int r = 0; r < 64; r++) { float v = on[r][t]; mx = fmaxf(mx, v); sm += v; }
        z[t] += mx; z[8 + t] += sm * (1.f / 64.f);
    }
    __syncthreads();
    if (t < 128) {
        float s = d1_b[t];
#pragma unroll
        for (int f = 0; f < 16; f++) s += z[f] * d1_w[t * 16 + f];
        z1[t] = lrelu(s);
    }
    __syncthreads();
    if (t < 64) {
        float s = d2_b[t];
        for (int f = 0; f < 128; f++) s += z1[f] * d2_w[t * 128 + f];
        z2[t] = lrelu(s);
    }
    __syncthreads();
    if (t == 0) {
        float s = d3_b[0];
        for (int f = 0; f < 64; f++) s += z2[f] * d3_w[f];
        out[b] = s;
    }
}

// ---------------- launcher ----------------
extern "C" void kernel_launch(void* const* d_in, const int* in_sizes, int n_in,
                              void* d_out, int out_size) {
    const float* x    = (const float*)d_in[0];
    const float* w1a  = (const float*)d_in[1];
    const float* b1a  = (const float*)d_in[2];
    const float* w1b  = (const float*)d_in[3];
    const float* b1b  = (const float*)d_in[4];
    const float* w2a  = (const float*)d_in[5];
    const float* b2a  = (const float*)d_in[6];
    const float* w2b  = (const float*)d_in[7];
    const float* b2b  = (const float*)d_in[8];
    const float* e2nw = (const float*)d_in[9];
    const float* e2nb = (const float*)d_in[10];
    const float* a11w = (const float*)d_in[11];
    const float* a11b = (const float*)d_in[12];
    const float* a12w = (const float*)d_in[13];
    const float* a12b = (const float*)d_in[14];
    const float* g1w  = (const float*)d_in[15];
    const float* g1b  = (const float*)d_in[16];
    const float* a21w = (const float*)d_in[17];
    const float* a21b = (const float*)d_in[18];
    const float* a22w = (const float*)d_in[19];
    const float* a22b = (const float*)d_in[20];
    const float* d1w  = (const float*)d_in[21];
    const float* d1b  = (const float*)d_in[22];
    const float* d2w  = (const float*)d_in[23];
    const float* d2b  = (const float*)d_in[24];
    const float* d3w  = (const float*)d_in[25];
    const float* d3b  = (const float*)d_in[26];

    // k2s smem: SWp 257*17*8 + svi 2048 + uk 2048 + segtot 1024 + OS 1152 + wtmp 256*17*4
    const int k2s_smem = 257 * 17 * 8 + 2048 + 2048 + 1024 + 1152 + 256 * 17 * 4;  // 58,632 B
    cudaFuncSetAttribute(k2s, cudaFuncAttributeMaxDynamicSharedMemorySize, k2s_smem);

    k1<<<dim3(8, 128), 256>>>(x, w1a, b1a, w1b, b1b);
    ks<<<dim3(8, 128), 256>>>();
    kz<<<16, 1024>>>();
    k2s<<<dim3(16, 16), 128, k2s_smem>>>(w2a, b2a, w2b, b2b);
    k3<<<dim3(8, 64), 256>>>(e2nw);
    k4<<<8, 256>>>(x, e2nb, a11w, a11b, a12w, a12b, g1w, g1b, a21w, a21b,
                   a22w, a22b, d1w, d1b, d2w, d2b, d3w, d3b, (float*)d_out);
}

// round 10
// speedup vs baseline: 5.6444x; 1.2377x over previous
#include <cuda_runtime.h>
#include <math.h>

typedef unsigned long long ull;
typedef unsigned int uint;
#define DV __device__ __forceinline__

// ---------------- scratch (device globals; no allocations) ----------------
__device__ float g_a1[8 * 128 * 256];
__device__ float g_b1[8 * 128 * 256];
__device__ float g_a2[8 * 256 * 256];
__device__ float g_b2[8 * 256 * 256];
__device__ float g_np[8 * 256 * 8];
__device__ float2 g_svi[2][8 * 128 * 256];  // [mode][(b*128+c)*256+k] = {sorted v, idx bits}
__device__ float2 g_uk[2][8 * 128 * 256];   // [mode][(b*128+c)*256+i] = {u, k bits}

DV float lrelu(float x) { return x > 0.f ? x : 0.33f * x; }
DV ull ffma2(ull a, ull b, ull c) {
    ull d; asm("fma.rn.f32x2 %0,%1,%2,%3;" : "=l"(d) : "l"(a), "l"(b), "l"(c)); return d;
}
DV ull pack2(float x, float y) {
    ull d; asm("mov.b64 %0,{%1,%2};" : "=l"(d) : "r"(__float_as_uint(x)), "r"(__float_as_uint(y))); return d;
}
DV float2 unpk(ull v) {
    float2 f; asm("mov.b64 {%0,%1},%2;" : "=f"(f.x), "=f"(f.y) : "l"(v)); return f;
}

// ---------------- k1: layer-1 rank terms (8-c tile: x traffic /8) ----------------
__global__ void __launch_bounds__(256) k1(const float* __restrict__ x,
                                          const float* __restrict__ w1a, const float* __restrict__ b1a,
                                          const float* __restrict__ w1b, const float* __restrict__ b1b) {
    __shared__ float wa[8][256], wb[8][256];
    int b = blockIdx.x, c0 = blockIdx.y * 8, t = threadIdx.x;
#pragma unroll
    for (int cc = 0; cc < 8; cc++) {
        wa[cc][t] = w1a[(c0 + cc) * 256 + t];
        wb[cc][t] = w1b[(c0 + cc) * 256 + t];
    }
    __syncthreads();
    const float* xb = x + b * 65536;
    float aA[8], aB[8];
#pragma unroll
    for (int cc = 0; cc < 8; cc++) { aA[cc] = 0.f; aB[cc] = 0.f; }
    const float4* xr = (const float4*)(xb + t * 256);
#pragma unroll 4
    for (int j4 = 0; j4 < 64; j4++) {
        float4 v = xr[j4];
#pragma unroll
        for (int cc = 0; cc < 8; cc++)
            aA[cc] += v.x * wa[cc][j4 * 4] + v.y * wa[cc][j4 * 4 + 1] +
                      v.z * wa[cc][j4 * 4 + 2] + v.w * wa[cc][j4 * 4 + 3];
    }
#pragma unroll 4
    for (int i = 0; i < 256; i++) {
        float xv = xb[i * 256 + t];
#pragma unroll
        for (int cc = 0; cc < 8; cc++) aB[cc] += xv * wb[cc][i];
    }
#pragma unroll
    for (int cc = 0; cc < 8; cc++) {
        g_a1[(b * 128 + c0 + cc) * 256 + t] = aA[cc] + b1a[c0 + cc];
        g_b1[(b * 128 + c0 + cc) * 256 + t] = aB[cc] + b1b[c0 + cc];
    }
}

// ---------------- ks: per-(b,c,mode) bitonic sort + thresholds ----------------
__global__ void __launch_bounds__(256) ks() {
    __shared__ float sv[256];
    __shared__ int si[256];
    int b = blockIdx.x, c = blockIdx.y, t = threadIdx.x;
    int mode = blockIdx.z;
    int base = (b * 128 + c) * 256;
    const float* varr = mode ? g_a1 : g_b1;
    const float* uarr = mode ? g_b1 : g_a1;
    sv[t] = varr[base + t];
    si[t] = t;
    __syncthreads();
    for (int k = 2; k <= 256; k <<= 1) {
        for (int j = k >> 1; j > 0; j >>= 1) {
            int ixj = t ^ j;
            if (ixj > t) {
                bool up = ((t & k) == 0);
                float v0 = sv[t], v1 = sv[ixj];
                if ((v0 > v1) == up) {
                    int i0 = si[t], i1 = si[ixj];
                    sv[t] = v1; sv[ixj] = v0;
                    si[t] = i1; si[ixj] = i0;
                }
            }
            __syncthreads();
        }
    }
    g_svi[mode][base + t] = make_float2(sv[t], __int_as_float(si[t]));
    float u = uarr[base + t];
    float nu = -u;
    int lo = 0, hi = 256;
#pragma unroll
    for (int it = 0; it < 8; it++) {
        int mid = (lo + hi) >> 1;
        if (sv[mid] <= nu) lo = mid + 1; else hi = mid;
    }
    g_uk[mode][base + t] = make_float2(u, __int_as_float(lo));
}

// ---------------- kz: zero the e2n accumulator ----------------
__global__ void kz() { g_np[blockIdx.x * 1024 + threadIdx.x] = 0.f; }

// ---------------- k2s: layer-2 via sorted suffix sums (16-p tiles, 256 thr, 16x16 segs) ----------------
__global__ void __launch_bounds__(256, 3) k2s(const float* __restrict__ w2a, const float* __restrict__ b2a,
                                              const float* __restrict__ w2b, const float* __restrict__ b2b) {
    extern __shared__ char smem_raw[];
    float2* SWp = (float2*)smem_raw;        // [257][17] raw suffix pairs
    float2* svi = SWp + 257 * 17;           // [256]
    float2* uk = svi + 256;                 // [256]
    float2* segtot = uk + 256;              // [16][16]
    float2* OS = segtot + 16 * 16;          // [17][16] per-seg offsets (row 16 = zeros)
    float* wtmp = (float*)(OS + 17 * 16);   // [256][17]

    int t = threadIdx.x;
    int p0 = blockIdx.x * 16;
    int bm = blockIdx.y, b = bm >> 1, mode = bm & 1;
    const float* W = mode ? w2b : w2a;
    const float* bias = mode ? b2b : b2a;
    const float2* gsvi = g_svi[mode] + b * 32768;
    const float2* guk = g_uk[mode] + b * 32768;
    float* outp = (mode ? g_b2 : g_a2) + b * 65536;

    int p = t & 15, seg = t >> 4;       // 16 segs x 16 k
    int wlp = t >> 4, wls = t & 15;     // W loader: 16 p rows x 16 k-groups

    if (t < 16) {
        SWp[256 * 17 + t] = make_float2(0.f, 0.f);   // k=256 empty suffix
        OS[16 * 16 + t] = make_float2(0.f, 0.f);     // offset row for ki=256
    }

    float acc[16];
#pragma unroll
    for (int m = 0; m < 16; m++) acc[m] = 0.f;

    const float* wbase = W + (size_t)(p0 + wlp) * 32768;

    for (int c = 0; c < 128; c++) {
        __syncthreads();
        svi[t] = gsvi[c * 256 + t];
        uk[t] = guk[c * 256 + t];
        const float* wrow = wbase + c * 256;
#pragma unroll
        for (int m = 0; m < 4; m++) {
            float4 f = *(const float4*)(wrow + m * 64 + wls * 4);
            int kb = m * 64 + wls * 4;
            wtmp[(kb + 0) * 17 + wlp] = f.x;
            wtmp[(kb + 1) * 17 + wlp] = f.y;
            wtmp[(kb + 2) * 17 + wlp] = f.z;
            wtmp[(kb + 3) * 17 + wlp] = f.w;
        }
        __syncthreads();
        // backward suffix scan in this thread's 16-k segment (reg-batched 8+8)
        float run = 0.f, runv = 0.f;
#pragma unroll
        for (int batch = 1; batch >= 0; batch--) {
            float2 sv8[8];
            float wv8[8];
#pragma unroll
            for (int e = 7; e >= 0; e--) sv8[e] = svi[seg * 16 + batch * 8 + e];
#pragma unroll
            for (int e = 7; e >= 0; e--) wv8[e] = wtmp[__float_as_int(sv8[e].y) * 17 + p];
#pragma unroll
            for (int e = 7; e >= 0; e--) {
                int kk = seg * 16 + batch * 8 + e;
                run += wv8[e];
                runv = fmaf(wv8[e], sv8[e].x, runv);
                SWp[kk * 17 + p] = make_float2(run, runv);
            }
        }
        segtot[seg * 16 + p] = make_float2(run, runv);
        __syncthreads();
        {
            float offw = 0.f, offv = 0.f;
            for (int s2 = seg + 1; s2 < 16; s2++) {
                float2 st = segtot[s2 * 16 + p];
                offw += st.x; offv += st.y;
            }
            OS[seg * 16 + p] = make_float2(offw, offv);
        }
        __syncthreads();
        float2 sw0r = SWp[p];
        float2 os0 = OS[p];
        float sw0x = sw0r.x + os0.x, sw0y = sw0r.y + os0.y;
#pragma unroll 4
        for (int m = 0; m < 16; m++) {
            int i = seg * 16 + m;
            float2 ukv = uk[i];
            int ki = __float_as_int(ukv.y);
            float2 s2 = SWp[ki * 17 + p];
            float2 os = OS[(ki >> 4) * 16 + p];
            float t1 = fmaf(ukv.x, s2.x + os.x, s2.y + os.y);
            float t0 = fmaf(ukv.x, sw0x, sw0y);
            acc[m] = fmaf(0.33f, t0, fmaf(1.0f - 0.33f, t1, acc[m]));
        }
    }
    float bs = bias[p0 + p];
    float* dst = outp + (size_t)(p0 + p) * 256 + seg * 16;
#pragma unroll
    for (int m = 0; m < 16; m += 4) {
        float4 o = make_float4(acc[m] + bs, acc[m + 1] + bs, acc[m + 2] + bs, acc[m + 3] + bs);
        *(float4*)(dst + m) = o;
    }
}

// ---------------- k3: e2n contraction ----------------
__global__ void __launch_bounds__(256) k3(const float* __restrict__ ew) {
    __shared__ float Bsm[256];
    __shared__ ull Esm[256 * 4];
    int b = blockIdx.x, pc = blockIdx.y, tid = threadIdx.x;
    ull a4[4] = {0ULL, 0ULL, 0ULL, 0ULL};
    for (int p = pc * 4; p < pc * 4 + 4; p++) {
        __syncthreads();
        Bsm[tid] = g_b2[(b * 256 + p) * 256 + tid];
        float e[8];
#pragma unroll
        for (int q = 0; q < 8; q++) e[q] = ew[q * 65536 + p * 256 + tid];
#pragma unroll
        for (int q = 0; q < 4; q++) Esm[tid * 4 + q] = pack2(e[2 * q], e[2 * q + 1]);
        __syncthreads();
        float ai = g_a2[(b * 256 + p) * 256 + tid];
#pragma unroll 4
        for (int j = 0; j < 256; j++) {
            float t = lrelu(ai + Bsm[j]);
            ull ts = pack2(t, t);
            const ull* er = &Esm[j * 4];
            a4[0] = ffma2(er[0], ts, a4[0]);
            a4[1] = ffma2(er[1], ts, a4[1]);
            a4[2] = ffma2(er[2], ts, a4[2]);
            a4[3] = ffma2(er[3], ts, a4[3]);
        }
    }
    float* dst = &g_np[b * 2048 + tid * 8];
#pragma unroll
    for (int q = 0; q < 4; q++) {
        float2 f = unpk(a4[q]);
        atomicAdd(dst + 2 * q, f.x);
        atomicAdd(dst + 2 * q + 1, f.y);
    }
}

// ---------------- k4: GCN / pooling / readout / MLP tail ----------------
__global__ void __launch_bounds__(256) k4(const float* __restrict__ x, const float* __restrict__ e2n_b,
    const float* __restrict__ a11_w, const float* __restrict__ a11_b,
    const float* __restrict__ a12_w, const float* __restrict__ a12_b,
    const float* __restrict__ g1_w,  const float* __restrict__ g1_b,
    const float* __restrict__ a21_w, const float* __restrict__ a21_b,
    const float* __restrict__ a22_w, const float* __restrict__ a22_b,
    const float* __restrict__ d1_w,  const float* __restrict__ d1_b,
    const float* __restrict__ d2_w,  const float* __restrict__ d2_b,
    const float* __restrict__ d3_w,  const float* __restrict__ d3_b,
    float* __restrict__ out) {
    __shared__ uint  m0[256][8];
    __shared__ float nod[256][8];
    __shared__ float dg0[256];
    __shared__ float tp[256];
    __shared__ float sc[256];
    __shared__ float t8[256][8];
    __shared__ int   sel[128];
    __shared__ float hg[128][8];
    __shared__ float on[128][8];
    __shared__ uint  m1[128][4];
    __shared__ float dg1[128];
    __shared__ float z[16];
    __shared__ float z1[128];
    __shared__ float z2[64];

    int b = blockIdx.x, t = threadIdx.x;
    const float* xb = x + b * 65536;
    // adjacency via ballot (coalesced 128B reads)
    {
        int w = t >> 5, l = t & 31;
        for (int r = 0; r < 32; r++) {
            int i = w * 32 + r;
            int d = 0;
#pragma unroll
            for (int w8 = 0; w8 < 8; w8++) {
                float xv = xb[i * 256 + w8 * 32 + l];
                uint u = __ballot_sync(0xffffffffu, xv > 0.f);
                if (l == 0) { m0[i][w8] = u; d += __popc(u); }
            }
            if (l == 0) dg0[i] = (float)d;
        }
#pragma unroll
        for (int f = 0; f < 8; f++) nod[t][f] = lrelu(g_np[b * 2048 + t * 8 + f] + e2n_b[f]);
    }
    __syncthreads();
    {
        float s = 0;
#pragma unroll
        for (int f = 0; f < 8; f++) s += nod[t][f] * a11_w[f];
        tp[t] = s / dg0[t];
    }
    __syncthreads();
    {
        float s = 0;
        for (int j = 0; j < 256; j++) if ((m0[t][j >> 5] >> (j & 31)) & 1) s += tp[j];
        sc[t] = lrelu(s + a11_b[0]);
    }
    __syncthreads();
    tp[t] = sc[t] * a12_w[0] / dg0[t];
    __syncthreads();
    {
        float s = 0;
        for (int j = 0; j < 256; j++) if ((m0[t][j >> 5] >> (j & 31)) & 1) s += tp[j];
        sc[t] = 1.f / (1.f + expf(-(s + a12_b[0])));
    }
    __syncthreads();
    {
        float my = sc[t]; int r = 0;
        for (int j = 0; j < 256; j++) {
            float vj = sc[j];
            r += (vj > my) || (vj == my && j < t);
        }
        if (r < 128) sel[r] = t;
    }
    __syncthreads();
    for (int idx = t; idx < 1024; idx += 256) {
        int r = idx >> 3, f = idx & 7; int i = sel[r];
        on[r][f] = nod[i][f] * (1.f + sc[i]);
    }
    if (t < 128) {
        int i = sel[t], d = 0;
#pragma unroll
        for (int w = 0; w < 4; w++) {
            uint u = 0;
            for (int l = 0; l < 32; l++) {
                int j = sel[w * 32 + l];
                u |= ((m0[i][j >> 5] >> (j & 31)) & 1u) << l;
            }
            m1[t][w] = u; d += __popc(u);
        }
        dg1[t] = (float)d;
    }
    __syncthreads();
    if (t < 8) {
        float mx = -1e30f, sm = 0;
        for (int r = 0; r < 128; r++) { float v = on[r][t]; mx = fmaxf(mx, v); sm += v; }
        z[t] = mx; z[8 + t] = sm * (1.f / 128.f);
    }
    __syncthreads();
    for (int idx = t; idx < 1024; idx += 256) {
        int r2 = idx >> 3, fo = idx & 7;
        float s = 0;
#pragma unroll
        for (int f = 0; f < 8; f++) s += on[r2][f] * g1_w[fo * 8 + f];
        t8[r2][fo] = s / dg1[r2];
    }
    __syncthreads();
    for (int idx = t; idx < 1024; idx += 256) {
        int r = idx >> 3, fo = idx & 7;
        float s = 0;
        for (int j = 0; j < 128; j++) if ((m1[r][j >> 5] >> (j & 31)) & 1) s += t8[j][fo];
        hg[r][fo] = s + g1_b[fo];
    }
    __syncthreads();
    if (t < 128) {
        float s = 0;
#pragma unroll
        for (int f = 0; f < 8; f++) s += hg[t][f] * a21_w[f];
        tp[t] = s / dg1[t];
    }
    __syncthreads();
    if (t < 128) {
        float s = 0;
        for (int j = 0; j < 128; j++) if ((m1[t][j >> 5] >> (j & 31)) & 1) s += tp[j];
        sc[t] = lrelu(s + a21_b[0]);
    }
    __syncthreads();
    if (t < 128) tp[t] = sc[t] * a22_w[0] / dg1[t];
    __syncthreads();
    if (t < 128) {
        float s = 0;
        for (int j = 0; j < 128; j++) if ((m1[t][j >> 5] >> (j & 31)) & 1) s += tp[j];
        sc[t] = 1.f / (1.f + expf(-(s + a22_b[0])));
    }
    __syncthreads();
    if (t < 128) {
        float my = sc[t]; int r = 0;
        for (int j = 0; j < 128; j++) {
            float vj = sc[j];
            r += (vj > my) || (vj == my && j < t);
        }
        if (r < 64) sel[r] = t;
    }
    __syncthreads();
    for (int idx = t; idx < 512; idx += 256) {
        int r = idx >> 3, f = idx & 7; int i = sel[r];
        on[r][f] = hg[i][f] * (1.f + sc[i]);
    }
    __syncthreads();
    if (t < 8) {
        float mx = -1e30f, sm = 0;
        for (int r = 0; r < 64; r++) { float v = on[r][t]; mx = fmaxf(mx, v); sm += v; }
        z[t] += mx; z[8 + t] += sm * (1.f / 64.f);
    }
    __syncthreads();
    if (t < 128) {
        float s = d1_b[t];
#pragma unroll
        for (int f = 0; f < 16; f++) s += z[f] * d1_w[t * 16 + f];
        z1[t] = lrelu(s);
    }
    __syncthreads();
    if (t < 64) {
        float s = d2_b[t];
        for (int f = 0; f < 128; f++) s += z1[f] * d2_w[t * 128 + f];
        z2[t] = lrelu(s);
    }
    __syncthreads();
    if (t == 0) {
        float s = d3_b[0];
        for (int f = 0; f < 64; f++) s += z2[f] * d3_w[f];
        out[b] = s;
    }
}

// ---------------- launcher ----------------
extern "C" void kernel_launch(void* const* d_in, const int* in_sizes, int n_in,
                              void* d_out, int out_size) {
    const float* x    = (const float*)d_in[0];
    const float* w1a  = (const float*)d_in[1];
    const float* b1a  = (const float*)d_in[2];
    const float* w1b  = (const float*)d_in[3];
    const float* b1b  = (const float*)d_in[4];
    const float* w2a  = (const float*)d_in[5];
    const float* b2a  = (const float*)d_in[6];
    const float* w2b  = (const float*)d_in[7];
    const float* b2b  = (const float*)d_in[8];
    const float* e2nw = (const float*)d_in[9];
    const float* e2nb = (const float*)d_in[10];
    const float* a11w = (const float*)d_in[11];
    const float* a11b = (const float*)d_in[12];
    const float* a12w = (const float*)d_in[13];
    const float* a12b = (const float*)d_in[14];
    const float* g1w  = (const float*)d_in[15];
    const float* g1b  = (const float*)d_in[16];
    const float* a21w = (const float*)d_in[17];
    const float* a21b = (const float*)d_in[18];
    const float* a22w = (const float*)d_in[19];
    const float* a22b = (const float*)d_in[20];
    const float* d1w  = (const float*)d_in[21];
    const float* d1b  = (const float*)d_in[22];
    const float* d2w  = (const float*)d_in[23];
    const float* d2b  = (const float*)d_in[24];
    const float* d3w  = (const float*)d_in[25];
    const float* d3b  = (const float*)d_in[26];

    // k2s smem: SWp 257*17*8 + svi 2048 + uk 2048 + segtot 2048 + OS 2176 + wtmp 256*17*4
    const int k2s_smem = 257 * 17 * 8 + 2048 + 2048 + 2048 + 2176 + 256 * 17 * 4;  // 60,680 B
    cudaFuncSetAttribute(k2s, cudaFuncAttributeMaxDynamicSharedMemorySize, k2s_smem);

    k1<<<dim3(8, 16), 256>>>(x, w1a, b1a, w1b, b1b);
    ks<<<dim3(8, 128, 2), 256>>>();
    kz<<<16, 1024>>>();
    k2s<<<dim3(16, 16), 256, k2s_smem>>>(w2a, b2a, w2b, b2b);
    k3<<<dim3(8, 64), 256>>>(e2nw);
    k4<<<8, 256>>>(x, e2nb, a11w, a11b, a12w, a12b, g1w, g1b, a21w, a21b,
                   a22w, a22b, d1w, d1b, d2w, d2b, d3w, d3b, (float*)d_out);
}